// round 11
// baseline (speedup 1.0000x reference)
#include <cuda_runtime.h>
#include <cstdint>
#include <cstddef>

#define BB 256
#define TT 2048
#define DD0 57
#define HH 16
#define NPOS (BB*TT)            // 524288
#define NGATE ((size_t)NPOS*64) // 33554432

typedef unsigned long long u64;

// ---------------- scratch (device globals, no allocation) ----------------
__device__ float g_xg0[NGATE + 512];             // layer-0 gate preacts [pos][unit][4] + pad
__device__ float g_h2[(size_t)NPOS * HH];        // final layer h (masked)
__device__ float g_stats[32];                    // [0:16) sum, [16:32) sumsq
__device__ float g_coef[68];                     // [0:64) w'[o][j], [64:68) b'[o]

// ---------------- helpers ---------------------------------------------------
__device__ __forceinline__ u64 pk2(float lo, float hi) {
    u64 r; asm("mov.b64 %0,{%1,%2};" : "=l"(r) : "f"(lo), "f"(hi)); return r;
}
__device__ __forceinline__ void upk2(float& lo, float& hi, u64 v) {
    asm("mov.b64 {%0,%1},%2;" : "=f"(lo), "=f"(hi) : "l"(v));
}
__device__ __forceinline__ u64 fma2(u64 a, u64 b, u64 c) {
    u64 r; asm("fma.rn.f32x2 %0,%1,%2,%3;" : "=l"(r) : "l"(a), "l"(b), "l"(c)); return r;
}
__device__ __forceinline__ u64 add2(u64 a, u64 b) {
    u64 r; asm("add.rn.f32x2 %0,%1,%2;" : "=l"(r) : "l"(a), "l"(b)); return r;
}
__device__ __forceinline__ float f_tanh(float x) {
    float r; asm("tanh.approx.f32 %0,%1;" : "=f"(r) : "f"(x)); return r;
}
__device__ __forceinline__ float f_sigm(float x) {
    float t = f_tanh(0.5f * x);
    return fmaf(0.5f, t, 0.5f);
}

// ---------------- layer-0 input projection (proven R6 kernel) --------------
// out layout: xg[pos*64 + (r&15)*4 + (r>>4)]  (per-unit float4 = i,f,g,o)
template<int DIN, int PPB>
__global__ void __launch_bounds__(256)
proj_kernel(const float* __restrict__ in,
            const float* __restrict__ W,
            const float* __restrict__ bih,
            const float* __restrict__ bhh,
            float* __restrict__ xg)
{
    constexpr int DPAD = (DIN % 2 == 0) ? (DIN + 1) : DIN;
    constexpr int XPAD = ((DIN + 3) / 4) * 4;
    __shared__ __align__(16) float sx[PPB * XPAD];
    __shared__ float sw[64 * DPAD];

    const int tid = threadIdx.x;
    const int r   = tid & 63;
    const int posBase = blockIdx.x * PPB;

    for (int i = tid; i < PPB * DIN; i += 256)
        sx[(i / DIN) * XPAD + (i % DIN)] = in[(size_t)posBase * DIN + i];
    for (int i = tid; i < 64 * DIN; i += 256)
        sw[(i / DIN) * DPAD + (i % DIN)] = W[i];
    __syncthreads();

    float w[DIN];
#pragma unroll
    for (int d = 0; d < DIN; ++d) w[d] = sw[r * DPAD + d];
    const float bias = __ldg(bih + r) + __ldg(bhh + r);
    const int outIdx = ((r & 15) << 2) | (r >> 4);

    constexpr int D4 = DIN / 4;
    for (int p = (tid >> 6); p < PPB; p += 4) {
        const float* xp = &sx[p * XPAD];
        float acc = bias;
#pragma unroll
        for (int d4 = 0; d4 < D4; ++d4) {
            float4 v = ((const float4*)xp)[d4];
            acc = fmaf(v.x, w[d4 * 4 + 0], acc);
            acc = fmaf(v.y, w[d4 * 4 + 1], acc);
            acc = fmaf(v.z, w[d4 * 4 + 2], acc);
            acc = fmaf(v.w, w[d4 * 4 + 3], acc);
        }
#pragma unroll
        for (int d = 4 * D4; d < DIN; ++d)
            acc = fmaf(xp[d], w[d], acc);
        xg[((size_t)(posBase + p) << 6) + outIdx] = acc;
    }
}

// ---------------- fused 3-layer diagonal scan -------------------------------
// CTA = 96 threads = 3 warps; warp l runs layer l for 2 batches (16 lanes each).
// Round r: warp l computes its time step t = r - l. Cross-layer handoff via
// parity-double-buffered shared hx + one __syncthreads per round.
__global__ void __launch_bounds__(96)
fused_scan(const float4* __restrict__ xg0,      // layer-0 preacts (prev launch)
           const float*  __restrict__ Whh0,
           const float*  __restrict__ Wih1, const float* __restrict__ Whh1,
           const float*  __restrict__ bih1, const float* __restrict__ bhh1,
           const float*  __restrict__ Wih2, const float* __restrict__ Whh2,
           const float*  __restrict__ bih2, const float* __restrict__ bhh2,
           const int*    __restrict__ lengths,
           float*        __restrict__ h2out)
{
    __shared__ __align__(16) float hx[2][3][32];   // [parity][layer][half*16+j]

    const int tid  = threadIdx.x;
    const int wid  = tid >> 5;        // layer
    const int lane = tid & 31;
    const int j    = lane & 15;
    const int half = lane >> 4;
    const int b    = blockIdx.x * 2 + half;

    // recurrent weights for this warp's layer, rows j,16+j,32+j,48+j -> gates i,f,g,o
    const float* Whh = (wid == 0) ? Whh0 : (wid == 1) ? Whh1 : Whh2;
    u64 whh[4][8];
#pragma unroll
    for (int g = 0; g < 4; ++g) {
        const float2* row = (const float2*)(Whh + (g * 16 + j) * 16);
#pragma unroll
        for (int m = 0; m < 8; ++m) {
            float2 v = __ldg(row + m);
            whh[g][m] = pk2(v.x, v.y);
        }
    }
    // input-projection weights + bias (layers 1,2 only)
    u64 wih[4][8];
    float bias[4];
    if (wid > 0) {
        const float* Wih = (wid == 1) ? Wih1 : Wih2;
        const float* bi  = (wid == 1) ? bih1 : bih2;
        const float* bh  = (wid == 1) ? bhh1 : bhh2;
#pragma unroll
        for (int g = 0; g < 4; ++g) {
            const float2* row = (const float2*)(Wih + (g * 16 + j) * 16);
#pragma unroll
            for (int m = 0; m < 8; ++m) {
                float2 v = __ldg(row + m);
                wih[g][m] = pk2(v.x, v.y);
            }
            bias[g] = __ldg(bi + g * 16 + j) + __ldg(bh + g * 16 + j);
        }
    }

    const int len = lengths[b];
    const float4* xp = xg0   + (size_t)b * TT * 16 + j;
    float*        hp = h2out + (size_t)b * TT * 16 + j;

    // zero both parity buffers (h(-1) = 0 for every layer)
    for (int i = tid; i < 192; i += 96) ((float*)hx)[i] = 0.0f;

    // warp-0 xg prefetch ring
    float4 buf[8];
    if (wid == 0) {
#pragma unroll
        for (int u = 0; u < 8; ++u) buf[u] = __ldg(xp + u * 16);
    }

    float c = 0.0f;

    for (int r = 0; r < TT + 2; ++r) {
        __syncthreads();                       // round barrier: r-1 writes -> r reads
        const int rp = r & 1, rq = rp ^ 1;
        const int t  = r - wid;
        if (t >= 0 && t < TT) {
            float4 cur;
            if (wid == 0) {
                cur = buf[r & 7];
                buf[r & 7] = __ldg(xp + (r + 8) * 16);   // padded array
            }
            // own h(t-1), broadcast as packed pairs
            const ulonglong2* q = (const ulonglong2*)&hx[rq][wid][half * 16];
            ulonglong2 q0 = q[0], q1 = q[1], q2 = q[2], q3 = q[3];

            u64 A0[4], A1[4];
#pragma unroll
            for (int g = 0; g < 4; ++g) {
                float a0 = (wid == 0)
                    ? ((g == 0) ? cur.x : (g == 1) ? cur.y : (g == 2) ? cur.z : cur.w)
                    : bias[g];
                u64 s0 = pk2(a0, 0.0f);
                s0 = fma2(q0.x, whh[g][0], s0);
                s0 = fma2(q0.y, whh[g][1], s0);
                s0 = fma2(q1.x, whh[g][2], s0);
                s0 = fma2(q1.y, whh[g][3], s0);
                u64 s1 = fma2(q2.x, whh[g][4], 0ull);
                s1 = fma2(q2.y, whh[g][5], s1);
                s1 = fma2(q3.x, whh[g][6], s1);
                s1 = fma2(q3.y, whh[g][7], s1);
                A0[g] = s0; A1[g] = s1;
            }
            if (wid > 0) {
                // h_{l-1}(t), written by warp wid-1 in round r-1 (parity rq)
                const ulonglong2* p = (const ulonglong2*)&hx[rq][wid - 1][half * 16];
                ulonglong2 p0 = p[0], p1 = p[1], p2 = p[2], p3 = p[3];
#pragma unroll
                for (int g = 0; g < 4; ++g) {
                    u64 s0 = A0[g], s1 = A1[g];
                    s0 = fma2(p0.x, wih[g][0], s0);
                    s0 = fma2(p0.y, wih[g][1], s0);
                    s0 = fma2(p1.x, wih[g][2], s0);
                    s0 = fma2(p1.y, wih[g][3], s0);
                    s1 = fma2(p2.x, wih[g][4], s1);
                    s1 = fma2(p2.y, wih[g][5], s1);
                    s1 = fma2(p3.x, wih[g][6], s1);
                    s1 = fma2(p3.y, wih[g][7], s1);
                    A0[g] = s0; A1[g] = s1;
                }
            }
            float lo0, hi0, lo1, hi1, lo2, hi2, lo3, hi3;
            upk2(lo0, hi0, add2(A0[0], A1[0])); float a_i = lo0 + hi0;
            upk2(lo1, hi1, add2(A0[1], A1[1])); float a_f = lo1 + hi1;
            upk2(lo2, hi2, add2(A0[2], A1[2])); float a_g = lo2 + hi2;
            upk2(lo3, hi3, add2(A0[3], A1[3])); float a_o = lo3 + hi3;

            float gi = f_sigm(a_i);
            float gf = f_sigm(a_f);
            float gg = f_tanh(a_g);
            float go = f_sigm(a_o);
            c = fmaf(gf, c, gi * gg);
            float hn = go * f_tanh(c);

            hx[rp][wid][half * 16 + j] = hn;     // publish (unmasked)
            if (wid == 2)
                hp[t * 16] = (t < len) ? hn : 0.0f;
        }
    }
}

// ---------------- BN stats --------------------------------------------------
__global__ void zero_stats_kernel() {
    if (threadIdx.x < 32) g_stats[threadIdx.x] = 0.0f;
}

__global__ void stats_kernel()
{
    __shared__ float ss[16], sq[16];
    int tid = threadIdx.x;
    if (tid < 16) { ss[tid] = 0.0f; sq[tid] = 0.0f; }
    __syncthreads();
    int j = tid & 15;
    int rpb = blockDim.x >> 4;
    float s = 0.0f, s2 = 0.0f;
    for (int pos = blockIdx.x * rpb + (tid >> 4); pos < NPOS; pos += gridDim.x * rpb) {
        float v = g_h2[(size_t)pos * 16 + j];
        s += v; s2 += v * v;
    }
    atomicAdd(&ss[j], s);
    atomicAdd(&sq[j], s2);
    __syncthreads();
    if (tid < 16) {
        atomicAdd(&g_stats[tid],      ss[tid]);
        atomicAdd(&g_stats[16 + tid], sq[tid]);
    }
}

// ---------------- fold BN into FC ------------------------------------------
__global__ void coef_kernel(const float* __restrict__ gamma,
                            const float* __restrict__ beta,
                            const float* __restrict__ fcw,
                            const float* __restrict__ fcb)
{
    __shared__ float scl[16], sht[16];
    int tid = threadIdx.x;
    if (tid < 16) {
        const float inv_n = 1.0f / (float)NPOS;
        float mean = g_stats[tid] * inv_n;
        float var  = g_stats[16 + tid] * inv_n - mean * mean;
        float s = rsqrtf(var + 1e-5f) * gamma[tid];
        scl[tid] = s;
        sht[tid] = beta[tid] - mean * s;
    }
    __syncthreads();
    if (tid < 64) {
        int o = tid >> 4, jj = tid & 15;
        g_coef[tid] = fcw[o * 16 + jj] * scl[jj];
    }
    if (tid < 4) {
        float bb = fcb[tid];
        for (int jj = 0; jj < 16; ++jj)
            bb += fcw[tid * 16 + jj] * sht[jj];
        g_coef[64 + tid] = bb;
    }
}

// ---------------- final GEMV ------------------------------------------------
__global__ void out_kernel(float* __restrict__ out)
{
    int pos = blockIdx.x * blockDim.x + threadIdx.x;
    if (pos >= NPOS) return;
    const float4* hp = (const float4*)(g_h2 + (size_t)pos * 16);
    float4 v0 = hp[0], v1 = hp[1], v2 = hp[2], v3 = hp[3];
    float hv[16] = { v0.x, v0.y, v0.z, v0.w, v1.x, v1.y, v1.z, v1.w,
                     v2.x, v2.y, v2.z, v2.w, v3.x, v3.y, v3.z, v3.w };
    float o0 = g_coef[64], o1 = g_coef[65], o2 = g_coef[66], o3 = g_coef[67];
#pragma unroll
    for (int jj = 0; jj < 16; ++jj) {
        float hvv = hv[jj];
        o0 = fmaf(hvv, g_coef[ 0 + jj], o0);
        o1 = fmaf(hvv, g_coef[16 + jj], o1);
        o2 = fmaf(hvv, g_coef[32 + jj], o2);
        o3 = fmaf(hvv, g_coef[48 + jj], o3);
    }
    float4 r = { o0, o1, o2, o3 };
    ((float4*)out)[pos] = r;
}

// ---------------- host ------------------------------------------------------
extern "C" void kernel_launch(void* const* d_in, const int* in_sizes, int n_in,
                              void* d_out, int out_size)
{
    const float* x    = (const float*)d_in[0];
    const int*   len  = (const int*)  d_in[1];
    const float* Wih0 = (const float*)d_in[2];
    const float* Whh0 = (const float*)d_in[3];
    const float* bih0 = (const float*)d_in[4];
    const float* bhh0 = (const float*)d_in[5];
    const float* Wih1 = (const float*)d_in[6];
    const float* Whh1 = (const float*)d_in[7];
    const float* bih1 = (const float*)d_in[8];
    const float* bhh1 = (const float*)d_in[9];
    const float* Wih2 = (const float*)d_in[10];
    const float* Whh2 = (const float*)d_in[11];
    const float* bih2 = (const float*)d_in[12];
    const float* bhh2 = (const float*)d_in[13];
    const float* gam  = (const float*)d_in[14];
    const float* bet  = (const float*)d_in[15];
    const float* fcw  = (const float*)d_in[16];
    const float* fcb  = (const float*)d_in[17];

    float *xg, *h2;
    cudaGetSymbolAddress((void**)&xg, g_xg0);
    cudaGetSymbolAddress((void**)&h2, g_h2);

    // layer-0 projection (no sequential dependency)
    proj_kernel<DD0, 64><<<NPOS / 64, 256>>>(x, Wih0, bih0, bhh0, xg);

    // fused diagonal 3-layer scan: 128 CTAs x 96 threads, 2 batches/CTA
    fused_scan<<<BB / 2, 96>>>((const float4*)xg, Whh0,
                               Wih1, Whh1, bih1, bhh1,
                               Wih2, Whh2, bih2, bhh2,
                               len, h2);

    // BN stats + fold into FC + output
    zero_stats_kernel<<<1, 32>>>();
    stats_kernel<<<1024, 256>>>();
    coef_kernel<<<1, 64>>>(gam, bet, fcw, fcb);
    out_kernel<<<NPOS / 256, 256>>>((float*)d_out);
}

// round 12
// speedup vs baseline: 1.0488x; 1.0488x over previous
#include <cuda_runtime.h>
#include <cstdint>
#include <cstddef>

#define BB 256
#define TT 2048
#define DD0 57
#define HH 16
#define NPOS (BB*TT)            // 524288
#define NGATE ((size_t)NPOS*64) // 33554432

typedef unsigned long long u64;

// ---------------- scratch (device globals, no allocation) ----------------
__device__ float g_xg0[NGATE + 512];             // layer-0 preacts [pos][half][unit][2] + 8-step pad
__device__ float g_h2[(size_t)NPOS * HH];        // final layer h (masked)
__device__ float g_stats[32];                    // [0:16) sum, [16:32) sumsq
__device__ float g_coef[68];                     // [0:64) w'[o][j], [64:68) b'[o]

// ---------------- helpers ---------------------------------------------------
__device__ __forceinline__ u64 pk2(float lo, float hi) {
    u64 r; asm("mov.b64 %0,{%1,%2};" : "=l"(r) : "f"(lo), "f"(hi)); return r;
}
__device__ __forceinline__ void upk2(float& lo, float& hi, u64 v) {
    asm("mov.b64 {%0,%1},%2;" : "=f"(lo), "=f"(hi) : "l"(v));
}
__device__ __forceinline__ u64 fma2(u64 a, u64 b, u64 c) {
    u64 r; asm("fma.rn.f32x2 %0,%1,%2,%3;" : "=l"(r) : "l"(a), "l"(b), "l"(c)); return r;
}
__device__ __forceinline__ u64 add2(u64 a, u64 b) {
    u64 r; asm("add.rn.f32x2 %0,%1,%2;" : "=l"(r) : "l"(a), "l"(b)); return r;
}
__device__ __forceinline__ float f_tanh(float x) {
    float r; asm("tanh.approx.f32 %0,%1;" : "=f"(r) : "f"(x)); return r;
}

// ---------------- layer-0 input projection ---------------------------------
// out layout (R5): xg[pos*64 + half*32 + unit*2 + (g&1)]
//   half0: (i_pre,f_pre) per unit ; half1: (g_pre,o_pre) per unit
template<int DIN, int PPB>
__global__ void __launch_bounds__(256)
proj_kernel(const float* __restrict__ in,
            const float* __restrict__ W,
            const float* __restrict__ bih,
            const float* __restrict__ bhh,
            float* __restrict__ xg)
{
    constexpr int DPAD = (DIN % 2 == 0) ? (DIN + 1) : DIN;
    constexpr int XPAD = ((DIN + 3) / 4) * 4;
    __shared__ __align__(16) float sx[PPB * XPAD];
    __shared__ float sw[64 * DPAD];

    const int tid = threadIdx.x;
    const int r   = tid & 63;
    const int posBase = blockIdx.x * PPB;

    for (int i = tid; i < PPB * DIN; i += 256)
        sx[(i / DIN) * XPAD + (i % DIN)] = in[(size_t)posBase * DIN + i];
    for (int i = tid; i < 64 * DIN; i += 256)
        sw[(i / DIN) * DPAD + (i % DIN)] = W[i];
    __syncthreads();

    float w[DIN];
#pragma unroll
    for (int d = 0; d < DIN; ++d) w[d] = sw[r * DPAD + d];
    const float bias = __ldg(bih + r) + __ldg(bhh + r);
    const int outIdx = ((r >> 5) << 5) | ((r & 15) << 1) | ((r >> 4) & 1);

    constexpr int D4 = DIN / 4;
    for (int p = (tid >> 6); p < PPB; p += 4) {
        const float* xp = &sx[p * XPAD];
        float acc = bias;
#pragma unroll
        for (int d4 = 0; d4 < D4; ++d4) {
            float4 v = ((const float4*)xp)[d4];
            acc = fmaf(v.x, w[d4 * 4 + 0], acc);
            acc = fmaf(v.y, w[d4 * 4 + 1], acc);
            acc = fmaf(v.z, w[d4 * 4 + 2], acc);
            acc = fmaf(v.w, w[d4 * 4 + 3], acc);
        }
#pragma unroll
        for (int d = 4 * D4; d < DIN; ++d)
            acc = fmaf(xp[d], w[d], acc);
        xg[((size_t)(posBase + p) << 6) + outIdx] = acc;
    }
}

// ---------------- fused 3-layer diagonal scan (half-split lanes) ------------
// CTA = 96 threads = 3 warps = 1 batch. Warp l runs layer l; round r computes
// t = r - l. Lanes 0-15: gates (i,f) of unit j; lanes 16-31: gates (g,o).
// Handoff via parity-double-buffered smem + 1 __syncthreads per round.
__global__ void __launch_bounds__(96)
fused_scan(const float2* __restrict__ xg0,
           const float*  __restrict__ Whh0,
           const float*  __restrict__ Wih1, const float* __restrict__ Whh1,
           const float*  __restrict__ bih1, const float* __restrict__ bhh1,
           const float*  __restrict__ Wih2, const float* __restrict__ Whh2,
           const float*  __restrict__ bih2, const float* __restrict__ bhh2,
           const int*    __restrict__ lengths,
           float*        __restrict__ h2out)
{
    __shared__ __align__(16) float hx[2][3][16];   // [parity][layer][unit]

    const int tid  = threadIdx.x;
    const int wid  = tid >> 5;        // layer
    const int lane = tid & 31;
    const int j    = lane & 15;
    const int half = lane >> 4;
    const int b    = blockIdx.x;

    // weight rows for this lane's 2 gates: row0 = i|g, row1 = f|o
    const int r0 = half * 32 + j;
    const int r1 = half * 32 + 16 + j;

    const float* Whh = (wid == 0) ? Whh0 : (wid == 1) ? Whh1 : Whh2;
    u64 wh0[8], wh1[8];
    {
        const float2* a = (const float2*)(Whh + r0 * 16);
        const float2* c = (const float2*)(Whh + r1 * 16);
#pragma unroll
        for (int m = 0; m < 8; ++m) {
            float2 v0 = __ldg(a + m), v1 = __ldg(c + m);
            wh0[m] = pk2(v0.x, v0.y);
            wh1[m] = pk2(v1.x, v1.y);
        }
    }
    u64 wx0[8], wx1[8];
    float bias0 = 0.0f, bias1 = 0.0f;
    if (wid > 0) {
        const float* Wih = (wid == 1) ? Wih1 : Wih2;
        const float* bi  = (wid == 1) ? bih1 : bih2;
        const float* bh  = (wid == 1) ? bhh1 : bhh2;
        const float2* a = (const float2*)(Wih + r0 * 16);
        const float2* c = (const float2*)(Wih + r1 * 16);
#pragma unroll
        for (int m = 0; m < 8; ++m) {
            float2 v0 = __ldg(a + m), v1 = __ldg(c + m);
            wx0[m] = pk2(v0.x, v0.y);
            wx1[m] = pk2(v1.x, v1.y);
        }
        bias0 = __ldg(bi + r0) + __ldg(bh + r0);
        bias1 = __ldg(bi + r1) + __ldg(bh + r1);
    }

    const int len = lengths[b];
    const float2* xp = xg0   + (size_t)b * TT * 32 + lane;
    float*        hp = h2out + (size_t)b * TT * 16 + j;

    // activation constants: gate0 is sigm on half0 (i), tanh on half1 (g)
    const float s0c = half ? 1.0f : 0.5f;
    const float m0c = half ? 1.0f : 0.5f;
    const float a0c = half ? 0.0f : 0.5f;

    // zero both parity buffers (h(-1)=0 all layers)
    for (int i = tid; i < 96; i += 96) ;  // (no-op keep tid use)
    if (tid < 96) { if (tid < 96) ((float*)hx)[tid] = 0.0f; }
    // hx has 2*3*16 = 96 floats: each thread zeroes one.

    float2 buf[8];
    if (wid == 0) {
#pragma unroll
        for (int u = 0; u < 8; ++u) buf[u] = __ldg(xp + u * 32);
    }

    float c = 0.0f;

    for (int r = 0; r < TT + 2; ++r) {
        __syncthreads();                       // round barrier
        const int rp = r & 1, rq = rp ^ 1;
        const int t  = r - wid;
        if (t >= 0 && t < TT) {
            float base0, base1;
            if (wid == 0) {
                float2 cur = buf[r & 7];
                buf[r & 7] = __ldg(xp + (r + 8) * 32);   // padded array
                base0 = cur.x; base1 = cur.y;
            } else {
                base0 = bias0; base1 = bias1;
            }

            // own h(t-1) as packed pairs
            const ulonglong2* q = (const ulonglong2*)&hx[rq][wid][0];
            ulonglong2 qa = q[0], qb = q[1];

            u64 s0a = fma2(qa.x, wh0[0], pk2(base0, 0.0f));
            u64 s1a = fma2(qa.x, wh1[0], pk2(base1, 0.0f));
            s0a = fma2(qa.y, wh0[1], s0a);  s1a = fma2(qa.y, wh1[1], s1a);
            s0a = fma2(qb.x, wh0[2], s0a);  s1a = fma2(qb.x, wh1[2], s1a);
            s0a = fma2(qb.y, wh0[3], s0a);  s1a = fma2(qb.y, wh1[3], s1a);
            u64 s0b = fma2(qa.x, 0ull, 0ull), s1b = 0ull;  // placeholder; re-use below
            {
                const ulonglong2* q2 = (const ulonglong2*)&hx[rq][wid][8];
                ulonglong2 qc = q2[0], qd = q2[1];
                s0b = fma2(qc.x, wh0[4], 0ull);  s1b = fma2(qc.x, wh1[4], 0ull);
                s0b = fma2(qc.y, wh0[5], s0b);   s1b = fma2(qc.y, wh1[5], s1b);
                s0b = fma2(qd.x, wh0[6], s0b);   s1b = fma2(qd.x, wh1[6], s1b);
                s0b = fma2(qd.y, wh0[7], s0b);   s1b = fma2(qd.y, wh1[7], s1b);
            }
            if (wid > 0) {
                // h_{l-1}(t) from warp wid-1 (written round r-1, parity rq)
                const ulonglong2* p = (const ulonglong2*)&hx[rq][wid - 1][0];
                ulonglong2 pa = p[0], pb = p[1];
                u64 x0a = fma2(pa.x, wx0[0], 0ull), x1a = fma2(pa.x, wx1[0], 0ull);
                x0a = fma2(pa.y, wx0[1], x0a);  x1a = fma2(pa.y, wx1[1], x1a);
                x0a = fma2(pb.x, wx0[2], x0a);  x1a = fma2(pb.x, wx1[2], x1a);
                x0a = fma2(pb.y, wx0[3], x0a);  x1a = fma2(pb.y, wx1[3], x1a);
                const ulonglong2* p2 = (const ulonglong2*)&hx[rq][wid - 1][8];
                ulonglong2 pc = p2[0], pd = p2[1];
                u64 x0b = fma2(pc.x, wx0[4], 0ull), x1b = fma2(pc.x, wx1[4], 0ull);
                x0b = fma2(pc.y, wx0[5], x0b);  x1b = fma2(pc.y, wx1[5], x1b);
                x0b = fma2(pd.x, wx0[6], x0b);  x1b = fma2(pd.x, wx1[6], x1b);
                x0b = fma2(pd.y, wx0[7], x0b);  x1b = fma2(pd.y, wx1[7], x1b);
                s0a = add2(s0a, x0a);  s1a = add2(s1a, x1a);
                s0b = add2(s0b, x0b);  s1b = add2(s1b, x1b);
            }
            float l0, h0, l1, h1;
            upk2(l0, h0, add2(s0a, s0b)); float a0 = l0 + h0;  // i | g
            upk2(l1, h1, add2(s1a, s1b)); float a1 = l1 + h1;  // f | o

            float g_l = fmaf(m0c, f_tanh(s0c * a0), a0c);      // sigm(i) | tanh(g)
            float g_h = fmaf(0.5f, f_tanh(0.5f * a1), 0.5f);   // sigm(f) | sigm(o)

            // exchange across halves: get the other 2 gates
            u64 own = pk2(g_l, g_h);
            double od = __shfl_xor_sync(0xffffffffu,
                                        __longlong_as_double((long long)own), 16);
            float ol, oh;
            upk2(ol, oh, (u64)__double_as_longlong(od));
            float gi = half ? ol  : g_l;
            float gf = half ? oh  : g_h;
            float gg = half ? g_l : ol;
            float go = half ? g_h : oh;

            c = fmaf(gf, c, gi * gg);
            float hn = go * f_tanh(c);

            if (half == 0) {
                hx[rp][wid][j] = hn;                 // publish
                if (wid == 2)
                    hp[t * 16] = (t < len) ? hn : 0.0f;
            }
        }
    }
}

// ---------------- BN stats --------------------------------------------------
__global__ void zero_stats_kernel() {
    if (threadIdx.x < 32) g_stats[threadIdx.x] = 0.0f;
}

__global__ void stats_kernel()
{
    __shared__ float ss[16], sq[16];
    int tid = threadIdx.x;
    if (tid < 16) { ss[tid] = 0.0f; sq[tid] = 0.0f; }
    __syncthreads();
    int j = tid & 15;
    int rpb = blockDim.x >> 4;
    float s = 0.0f, s2 = 0.0f;
    for (int pos = blockIdx.x * rpb + (tid >> 4); pos < NPOS; pos += gridDim.x * rpb) {
        float v = g_h2[(size_t)pos * 16 + j];
        s += v; s2 += v * v;
    }
    atomicAdd(&ss[j], s);
    atomicAdd(&sq[j], s2);
    __syncthreads();
    if (tid < 16) {
        atomicAdd(&g_stats[tid],      ss[tid]);
        atomicAdd(&g_stats[16 + tid], sq[tid]);
    }
}

// ---------------- fold BN into FC ------------------------------------------
__global__ void coef_kernel(const float* __restrict__ gamma,
                            const float* __restrict__ beta,
                            const float* __restrict__ fcw,
                            const float* __restrict__ fcb)
{
    __shared__ float scl[16], sht[16];
    int tid = threadIdx.x;
    if (tid < 16) {
        const float inv_n = 1.0f / (float)NPOS;
        float mean = g_stats[tid] * inv_n;
        float var  = g_stats[16 + tid] * inv_n - mean * mean;
        float s = rsqrtf(var + 1e-5f) * gamma[tid];
        scl[tid] = s;
        sht[tid] = beta[tid] - mean * s;
    }
    __syncthreads();
    if (tid < 64) {
        int o = tid >> 4, jj = tid & 15;
        g_coef[tid] = fcw[o * 16 + jj] * scl[jj];
    }
    if (tid < 4) {
        float bb = fcb[tid];
        for (int jj = 0; jj < 16; ++jj)
            bb += fcw[tid * 16 + jj] * sht[jj];
        g_coef[64 + tid] = bb;
    }
}

// ---------------- final GEMV ------------------------------------------------
__global__ void out_kernel(float* __restrict__ out)
{
    int pos = blockIdx.x * blockDim.x + threadIdx.x;
    if (pos >= NPOS) return;
    const float4* hp = (const float4*)(g_h2 + (size_t)pos * 16);
    float4 v0 = hp[0], v1 = hp[1], v2 = hp[2], v3 = hp[3];
    float hv[16] = { v0.x, v0.y, v0.z, v0.w, v1.x, v1.y, v1.z, v1.w,
                     v2.x, v2.y, v2.z, v2.w, v3.x, v3.y, v3.z, v3.w };
    float o0 = g_coef[64], o1 = g_coef[65], o2 = g_coef[66], o3 = g_coef[67];
#pragma unroll
    for (int jj = 0; jj < 16; ++jj) {
        float hvv = hv[jj];
        o0 = fmaf(hvv, g_coef[ 0 + jj], o0);
        o1 = fmaf(hvv, g_coef[16 + jj], o1);
        o2 = fmaf(hvv, g_coef[32 + jj], o2);
        o3 = fmaf(hvv, g_coef[48 + jj], o3);
    }
    float4 r = { o0, o1, o2, o3 };
    ((float4*)out)[pos] = r;
}

// ---------------- host ------------------------------------------------------
extern "C" void kernel_launch(void* const* d_in, const int* in_sizes, int n_in,
                              void* d_out, int out_size)
{
    const float* x    = (const float*)d_in[0];
    const int*   len  = (const int*)  d_in[1];
    const float* Wih0 = (const float*)d_in[2];
    const float* Whh0 = (const float*)d_in[3];
    const float* bih0 = (const float*)d_in[4];
    const float* bhh0 = (const float*)d_in[5];
    const float* Wih1 = (const float*)d_in[6];
    const float* Whh1 = (const float*)d_in[7];
    const float* bih1 = (const float*)d_in[8];
    const float* bhh1 = (const float*)d_in[9];
    const float* Wih2 = (const float*)d_in[10];
    const float* Whh2 = (const float*)d_in[11];
    const float* bih2 = (const float*)d_in[12];
    const float* bhh2 = (const float*)d_in[13];
    const float* gam  = (const float*)d_in[14];
    const float* bet  = (const float*)d_in[15];
    const float* fcw  = (const float*)d_in[16];
    const float* fcb  = (const float*)d_in[17];

    float *xg, *h2;
    cudaGetSymbolAddress((void**)&xg, g_xg0);
    cudaGetSymbolAddress((void**)&h2, g_h2);

    // layer-0 projection
    proj_kernel<DD0, 64><<<NPOS / 64, 256>>>(x, Wih0, bih0, bhh0, xg);

    // fused diagonal 3-layer scan: 256 CTAs x 96 threads, 1 batch/CTA
    fused_scan<<<BB, 96>>>((const float2*)xg, Whh0,
                           Wih1, Whh1, bih1, bhh1,
                           Wih2, Whh2, bih2, bhh2,
                           len, h2);

    // BN stats + fold into FC + output
    zero_stats_kernel<<<1, 32>>>();
    stats_kernel<<<1024, 256>>>();
    coef_kernel<<<1, 64>>>(gam, bet, fcw, fcb);
    out_kernel<<<NPOS / 256, 256>>>((float*)d_out);
}

// round 13
// speedup vs baseline: 1.2250x; 1.1681x over previous
#include <cuda_runtime.h>
#include <cstdint>
#include <cstddef>

#define BB 256
#define TT 2048
#define DD0 57
#define HH 16
#define NPOS (BB*TT)            // 524288
#define NGATE ((size_t)NPOS*64) // 33554432

typedef unsigned long long u64;

// ---------------- scratch (device globals, no allocation) ----------------
__device__ float g_xg0[NGATE + 4096];            // layer-0 preacts [pos][half][unit][2] + deep pad
__device__ float g_h2[(size_t)NPOS * HH];        // final layer h (masked)
__device__ float g_stats[32];                    // [0:16) sum, [16:32) sumsq
__device__ float g_coef[68];                     // [0:64) w'[o][j], [64:68) b'[o]

// ---------------- helpers ---------------------------------------------------
__device__ __forceinline__ u64 pk2(float lo, float hi) {
    u64 r; asm("mov.b64 %0,{%1,%2};" : "=l"(r) : "f"(lo), "f"(hi)); return r;
}
__device__ __forceinline__ void upk2(float& lo, float& hi, u64 v) {
    asm("mov.b64 {%0,%1},%2;" : "=f"(lo), "=f"(hi) : "l"(v));
}
__device__ __forceinline__ u64 fma2(u64 a, u64 b, u64 c) {
    u64 r; asm("fma.rn.f32x2 %0,%1,%2,%3;" : "=l"(r) : "l"(a), "l"(b), "l"(c)); return r;
}
__device__ __forceinline__ u64 add2(u64 a, u64 b) {
    u64 r; asm("add.rn.f32x2 %0,%1,%2;" : "=l"(r) : "l"(a), "l"(b)); return r;
}
__device__ __forceinline__ float f_tanh(float x) {
    float r; asm("tanh.approx.f32 %0,%1;" : "=f"(r) : "f"(x)); return r;
}

// ---------------- layer-0 input projection ---------------------------------
// out layout: xg[pos*64 + half*32 + unit*2 + (g&1)]
//   half0: (i_pre,f_pre) per unit ; half1: (g_pre,o_pre) per unit
template<int DIN, int PPB>
__global__ void __launch_bounds__(256)
proj_kernel(const float* __restrict__ in,
            const float* __restrict__ W,
            const float* __restrict__ bih,
            const float* __restrict__ bhh,
            float* __restrict__ xg)
{
    constexpr int DPAD = (DIN % 2 == 0) ? (DIN + 1) : DIN;
    constexpr int XPAD = ((DIN + 3) / 4) * 4;
    __shared__ __align__(16) float sx[PPB * XPAD];
    __shared__ float sw[64 * DPAD];

    const int tid = threadIdx.x;
    const int r   = tid & 63;
    const int posBase = blockIdx.x * PPB;

    for (int i = tid; i < PPB * DIN; i += 256)
        sx[(i / DIN) * XPAD + (i % DIN)] = in[(size_t)posBase * DIN + i];
    for (int i = tid; i < 64 * DIN; i += 256)
        sw[(i / DIN) * DPAD + (i % DIN)] = W[i];
    __syncthreads();

    float w[DIN];
#pragma unroll
    for (int d = 0; d < DIN; ++d) w[d] = sw[r * DPAD + d];
    const float bias = __ldg(bih + r) + __ldg(bhh + r);
    const int outIdx = ((r >> 5) << 5) | ((r & 15) << 1) | ((r >> 4) & 1);

    constexpr int D4 = DIN / 4;
    for (int p = (tid >> 6); p < PPB; p += 4) {
        const float* xp = &sx[p * XPAD];
        float acc = bias;
#pragma unroll
        for (int d4 = 0; d4 < D4; ++d4) {
            float4 v = ((const float4*)xp)[d4];
            acc = fmaf(v.x, w[d4 * 4 + 0], acc);
            acc = fmaf(v.y, w[d4 * 4 + 1], acc);
            acc = fmaf(v.z, w[d4 * 4 + 2], acc);
            acc = fmaf(v.w, w[d4 * 4 + 3], acc);
        }
#pragma unroll
        for (int d = 4 * D4; d < DIN; ++d)
            acc = fmaf(xp[d], w[d], acc);
        xg[((size_t)(posBase + p) << 6) + outIdx] = acc;
    }
}

// ---------------- fused 3-layer diagonal scan (half-split lanes) ------------
// CTA = 96 threads = 3 warps = 1 batch. Warp l runs layer l; round r computes
// t = r - l. Lanes 0-15: gates (i,f) of unit j; lanes 16-31: gates (g,o).
// Round loop unrolled x8 so the xg prefetch ring stays in REGISTERS with 8
// rounds of LDG slack (the R12 version spilled it to local and serialized
// a 577-cycle DRAM latency into every round via the round barrier).
__global__ void __launch_bounds__(96)
fused_scan(const float2* __restrict__ xg0,
           const float*  __restrict__ Whh0,
           const float*  __restrict__ Wih1, const float* __restrict__ Whh1,
           const float*  __restrict__ bih1, const float* __restrict__ bhh1,
           const float*  __restrict__ Wih2, const float* __restrict__ Whh2,
           const float*  __restrict__ bih2, const float* __restrict__ bhh2,
           const int*    __restrict__ lengths,
           float*        __restrict__ h2out)
{
    __shared__ __align__(16) float hx[2][3][16];   // [parity][layer][unit]

    const int tid  = threadIdx.x;
    const int wid  = tid >> 5;        // layer
    const int lane = tid & 31;
    const int j    = lane & 15;
    const int half = lane >> 4;
    const int b    = blockIdx.x;

    // weight rows for this lane's 2 gates: row0 = i|g, row1 = f|o
    const int r0 = half * 32 + j;
    const int r1 = half * 32 + 16 + j;

    const float* Whh = (wid == 0) ? Whh0 : (wid == 1) ? Whh1 : Whh2;
    u64 wh0[8], wh1[8];
    {
        const float2* a = (const float2*)(Whh + r0 * 16);
        const float2* c = (const float2*)(Whh + r1 * 16);
#pragma unroll
        for (int m = 0; m < 8; ++m) {
            float2 v0 = __ldg(a + m), v1 = __ldg(c + m);
            wh0[m] = pk2(v0.x, v0.y);
            wh1[m] = pk2(v1.x, v1.y);
        }
    }
    u64 wx0[8], wx1[8];
    float bias0 = 0.0f, bias1 = 0.0f;
    if (wid > 0) {
        const float* Wih = (wid == 1) ? Wih1 : Wih2;
        const float* bi  = (wid == 1) ? bih1 : bih2;
        const float* bh  = (wid == 1) ? bhh1 : bhh2;
        const float2* a = (const float2*)(Wih + r0 * 16);
        const float2* c = (const float2*)(Wih + r1 * 16);
#pragma unroll
        for (int m = 0; m < 8; ++m) {
            float2 v0 = __ldg(a + m), v1 = __ldg(c + m);
            wx0[m] = pk2(v0.x, v0.y);
            wx1[m] = pk2(v1.x, v1.y);
        }
        bias0 = __ldg(bi + r0) + __ldg(bh + r0);
        bias1 = __ldg(bi + r1) + __ldg(bh + r1);
    }

    const int len = lengths[b];
    const float2* xp = xg0   + (size_t)b * TT * 32 + lane;
    float*        hp = h2out + (size_t)b * TT * 16 + j;

    // activation constants: gate0 is sigm on half0 (i), tanh on half1 (g)
    const float s0c = half ? 1.0f : 0.5f;
    const float m0c = half ? 1.0f : 0.5f;
    const float a0c = half ? 0.0f : 0.5f;

    // zero both parity buffers (h(-1)=0 all layers); 2*3*16 = 96 floats
    ((float*)hx)[tid] = 0.0f;

    float2 buf[8];
    if (wid == 0) {
#pragma unroll
        for (int u = 0; u < 8; ++u) buf[u] = __ldg(xp + u * 32);
    }

    float c = 0.0f;

    for (int rb = 0; rb < TT + 8; rb += 8) {
#pragma unroll
        for (int u = 0; u < 8; ++u) {
            const int r = rb + u;
            __syncthreads();                   // round barrier
            const int rp = r & 1, rq = rp ^ 1;
            const int t  = r - wid;
            if (t >= 0 && t < TT) {
                float base0, base1;
                if (wid == 0) {
                    float2 cur = buf[u];       // static index -> registers
                    buf[u] = __ldg(xp + (r + 8) * 32);   // 8-round slack, padded
                    base0 = cur.x; base1 = cur.y;
                } else {
                    base0 = bias0; base1 = bias1;
                }

                // own h(t-1) as packed pairs
                const ulonglong2* q = (const ulonglong2*)&hx[rq][wid][0];
                ulonglong2 qa = q[0], qb = q[1], qc = q[2], qd = q[3];

                u64 s0a = fma2(qa.x, wh0[0], pk2(base0, 0.0f));
                u64 s1a = fma2(qa.x, wh1[0], pk2(base1, 0.0f));
                s0a = fma2(qa.y, wh0[1], s0a);  s1a = fma2(qa.y, wh1[1], s1a);
                s0a = fma2(qb.x, wh0[2], s0a);  s1a = fma2(qb.x, wh1[2], s1a);
                s0a = fma2(qb.y, wh0[3], s0a);  s1a = fma2(qb.y, wh1[3], s1a);
                u64 s0b = fma2(qc.x, wh0[4], 0ull);
                u64 s1b = fma2(qc.x, wh1[4], 0ull);
                s0b = fma2(qc.y, wh0[5], s0b);  s1b = fma2(qc.y, wh1[5], s1b);
                s0b = fma2(qd.x, wh0[6], s0b);  s1b = fma2(qd.x, wh1[6], s1b);
                s0b = fma2(qd.y, wh0[7], s0b);  s1b = fma2(qd.y, wh1[7], s1b);

                if (wid > 0) {
                    // h_{l-1}(t) from warp wid-1 (written round r-1, parity rq)
                    const ulonglong2* p = (const ulonglong2*)&hx[rq][wid - 1][0];
                    ulonglong2 pa = p[0], pb = p[1], pc = p[2], pd = p[3];
                    u64 x0a = fma2(pa.x, wx0[0], 0ull), x1a = fma2(pa.x, wx1[0], 0ull);
                    x0a = fma2(pa.y, wx0[1], x0a);  x1a = fma2(pa.y, wx1[1], x1a);
                    x0a = fma2(pb.x, wx0[2], x0a);  x1a = fma2(pb.x, wx1[2], x1a);
                    x0a = fma2(pb.y, wx0[3], x0a);  x1a = fma2(pb.y, wx1[3], x1a);
                    u64 x0b = fma2(pc.x, wx0[4], 0ull), x1b = fma2(pc.x, wx1[4], 0ull);
                    x0b = fma2(pc.y, wx0[5], x0b);  x1b = fma2(pc.y, wx1[5], x1b);
                    x0b = fma2(pd.x, wx0[6], x0b);  x1b = fma2(pd.x, wx1[6], x1b);
                    x0b = fma2(pd.y, wx0[7], x0b);  x1b = fma2(pd.y, wx1[7], x1b);
                    s0a = add2(s0a, x0a);  s1a = add2(s1a, x1a);
                    s0b = add2(s0b, x0b);  s1b = add2(s1b, x1b);
                }
                float l0, h0, l1, h1;
                upk2(l0, h0, add2(s0a, s0b)); float a0 = l0 + h0;  // i | g
                upk2(l1, h1, add2(s1a, s1b)); float a1 = l1 + h1;  // f | o

                float g_l = fmaf(m0c, f_tanh(s0c * a0), a0c);      // sigm(i) | tanh(g)
                float g_h = fmaf(0.5f, f_tanh(0.5f * a1), 0.5f);   // sigm(f) | sigm(o)

                // exchange across halves: get the other 2 gates
                u64 own = pk2(g_l, g_h);
                double od = __shfl_xor_sync(0xffffffffu,
                                            __longlong_as_double((long long)own), 16);
                float ol, oh;
                upk2(ol, oh, (u64)__double_as_longlong(od));
                float gi = half ? ol  : g_l;
                float gf = half ? oh  : g_h;
                float gg = half ? g_l : ol;
                float go = half ? g_h : oh;

                c = fmaf(gf, c, gi * gg);
                float hn = go * f_tanh(c);

                if (half == 0) {
                    hx[rp][wid][j] = hn;                 // publish
                    if (wid == 2)
                        hp[t * 16] = (t < len) ? hn : 0.0f;
                }
            }
        }
    }
}

// ---------------- BN stats --------------------------------------------------
__global__ void zero_stats_kernel() {
    if (threadIdx.x < 32) g_stats[threadIdx.x] = 0.0f;
}

__global__ void stats_kernel()
{
    __shared__ float ss[16], sq[16];
    int tid = threadIdx.x;
    if (tid < 16) { ss[tid] = 0.0f; sq[tid] = 0.0f; }
    __syncthreads();
    int j = tid & 15;
    int rpb = blockDim.x >> 4;
    float s = 0.0f, s2 = 0.0f;
    for (int pos = blockIdx.x * rpb + (tid >> 4); pos < NPOS; pos += gridDim.x * rpb) {
        float v = g_h2[(size_t)pos * 16 + j];
        s += v; s2 += v * v;
    }
    atomicAdd(&ss[j], s);
    atomicAdd(&sq[j], s2);
    __syncthreads();
    if (tid < 16) {
        atomicAdd(&g_stats[tid],      ss[tid]);
        atomicAdd(&g_stats[16 + tid], sq[tid]);
    }
}

// ---------------- fold BN into FC ------------------------------------------
__global__ void coef_kernel(const float* __restrict__ gamma,
                            const float* __restrict__ beta,
                            const float* __restrict__ fcw,
                            const float* __restrict__ fcb)
{
    __shared__ float scl[16], sht[16];
    int tid = threadIdx.x;
    if (tid < 16) {
        const float inv_n = 1.0f / (float)NPOS;
        float mean = g_stats[tid] * inv_n;
        float var  = g_stats[16 + tid] * inv_n - mean * mean;
        float s = rsqrtf(var + 1e-5f) * gamma[tid];
        scl[tid] = s;
        sht[tid] = beta[tid] - mean * s;
    }
    __syncthreads();
    if (tid < 64) {
        int o = tid >> 4, jj = tid & 15;
        g_coef[tid] = fcw[o * 16 + jj] * scl[jj];
    }
    if (tid < 4) {
        float bb = fcb[tid];
        for (int jj = 0; jj < 16; ++jj)
            bb += fcw[tid * 16 + jj] * sht[jj];
        g_coef[64 + tid] = bb;
    }
}

// ---------------- final GEMV ------------------------------------------------
__global__ void out_kernel(float* __restrict__ out)
{
    int pos = blockIdx.x * blockDim.x + threadIdx.x;
    if (pos >= NPOS) return;
    const float4* hp = (const float4*)(g_h2 + (size_t)pos * 16);
    float4 v0 = hp[0], v1 = hp[1], v2 = hp[2], v3 = hp[3];
    float hv[16] = { v0.x, v0.y, v0.z, v0.w, v1.x, v1.y, v1.z, v1.w,
                     v2.x, v2.y, v2.z, v2.w, v3.x, v3.y, v3.z, v3.w };
    float o0 = g_coef[64], o1 = g_coef[65], o2 = g_coef[66], o3 = g_coef[67];
#pragma unroll
    for (int jj = 0; jj < 16; ++jj) {
        float hvv = hv[jj];
        o0 = fmaf(hvv, g_coef[ 0 + jj], o0);
        o1 = fmaf(hvv, g_coef[16 + jj], o1);
        o2 = fmaf(hvv, g_coef[32 + jj], o2);
        o3 = fmaf(hvv, g_coef[48 + jj], o3);
    }
    float4 r = { o0, o1, o2, o3 };
    ((float4*)out)[pos] = r;
}

// ---------------- host ------------------------------------------------------
extern "C" void kernel_launch(void* const* d_in, const int* in_sizes, int n_in,
                              void* d_out, int out_size)
{
    const float* x    = (const float*)d_in[0];
    const int*   len  = (const int*)  d_in[1];
    const float* Wih0 = (const float*)d_in[2];
    const float* Whh0 = (const float*)d_in[3];
    const float* bih0 = (const float*)d_in[4];
    const float* bhh0 = (const float*)d_in[5];
    const float* Wih1 = (const float*)d_in[6];
    const float* Whh1 = (const float*)d_in[7];
    const float* bih1 = (const float*)d_in[8];
    const float* bhh1 = (const float*)d_in[9];
    const float* Wih2 = (const float*)d_in[10];
    const float* Whh2 = (const float*)d_in[11];
    const float* bih2 = (const float*)d_in[12];
    const float* bhh2 = (const float*)d_in[13];
    const float* gam  = (const float*)d_in[14];
    const float* bet  = (const float*)d_in[15];
    const float* fcw  = (const float*)d_in[16];
    const float* fcb  = (const float*)d_in[17];

    float *xg, *h2;
    cudaGetSymbolAddress((void**)&xg, g_xg0);
    cudaGetSymbolAddress((void**)&h2, g_h2);

    // layer-0 projection
    proj_kernel<DD0, 64><<<NPOS / 64, 256>>>(x, Wih0, bih0, bhh0, xg);

    // fused diagonal 3-layer scan: 256 CTAs x 96 threads, 1 batch/CTA
    fused_scan<<<BB, 96>>>((const float2*)xg, Whh0,
                           Wih1, Whh1, bih1, bhh1,
                           Wih2, Whh2, bih2, bhh2,
                           len, h2);

    // BN stats + fold into FC + output
    zero_stats_kernel<<<1, 32>>>();
    stats_kernel<<<1024, 256>>>();
    coef_kernel<<<1, 64>>>(gam, bet, fcw, fcb);
    out_kernel<<<NPOS / 256, 256>>>((float*)d_out);
}

// round 14
// speedup vs baseline: 2.3547x; 1.9221x over previous
#include <cuda_runtime.h>
#include <cstdint>
#include <cstddef>

#define BB 256
#define TT 2048
#define DD0 57
#define HH 16
#define NPOS (BB*TT)            // 524288
#define NGATE ((size_t)NPOS*64) // 33554432
#define CSTEP 128
#define NCHUNK 16

typedef unsigned long long u64;

// ---------------- scratch (device globals, no allocation) ----------------
__device__ float g_xg0[NGATE + 4096];
__device__ float g_xg1[NGATE + 4096];
__device__ float g_xg2[NGATE + 4096];
__device__ float g_h0[(size_t)NPOS * HH];
__device__ float g_h1[(size_t)NPOS * HH];
__device__ float g_h2[(size_t)NPOS * HH];
__device__ float g_cst[3 * BB * HH];             // carried cell state per layer
__device__ float g_hst[3 * BB * HH];             // carried hidden state per layer
__device__ float g_stats[32];
__device__ float g_coef[68];

// ---------------- helpers ---------------------------------------------------
__device__ __forceinline__ u64 pk2(float lo, float hi) {
    u64 r; asm("mov.b64 %0,{%1,%2};" : "=l"(r) : "f"(lo), "f"(hi)); return r;
}
__device__ __forceinline__ void upk2(float& lo, float& hi, u64 v) {
    asm("mov.b64 {%0,%1},%2;" : "=f"(lo), "=f"(hi) : "l"(v));
}
__device__ __forceinline__ u64 fma2(u64 a, u64 b, u64 c) {
    u64 r; asm("fma.rn.f32x2 %0,%1,%2,%3;" : "=l"(r) : "l"(a), "l"(b), "l"(c)); return r;
}
__device__ __forceinline__ u64 add2(u64 a, u64 b) {
    u64 r; asm("add.rn.f32x2 %0,%1,%2;" : "=l"(r) : "l"(a), "l"(b)); return r;
}
__device__ __forceinline__ float f_tanh(float x) {
    float r; asm("tanh.approx.f32 %0,%1;" : "=f"(r) : "f"(x)); return r;
}
__device__ __forceinline__ float f_sigm(float x) {
    float t = f_tanh(0.5f * x);
    return fmaf(0.5f, t, 0.5f);
}

// ---------------- chunked input projection (R6 core) ------------------------
// 64 positions per block; grid = BB*2 blocks per chunk.
// out layout: xg[pos*64 + (r&15)*4 + (r>>4)]  (per-unit float4 = i,f,g,o)
template<int DIN>
__global__ void __launch_bounds__(256)
proj_chunk(const float* __restrict__ in,
           const float* __restrict__ W,
           const float* __restrict__ bih,
           const float* __restrict__ bhh,
           float* __restrict__ xg,
           int chunk)
{
    constexpr int DPAD = (DIN % 2 == 0) ? (DIN + 1) : DIN;
    constexpr int XPAD = ((DIN + 3) / 4) * 4;
    __shared__ __align__(16) float sx[64 * XPAD];
    __shared__ float sw[64 * DPAD];

    const int tid = threadIdx.x;
    const int r   = tid & 63;
    const int bid = blockIdx.x;
    const int b   = bid >> 1;
    const int sub = bid & 1;
    const size_t posBase = (size_t)b * TT + chunk * CSTEP + sub * 64;

    for (int i = tid; i < 64 * DIN; i += 256)
        sx[(i / DIN) * XPAD + (i % DIN)] = in[posBase * DIN + i];
    for (int i = tid; i < 64 * DIN; i += 256)
        sw[(i / DIN) * DPAD + (i % DIN)] = W[i];
    __syncthreads();

    float w[DIN];
#pragma unroll
    for (int d = 0; d < DIN; ++d) w[d] = sw[r * DPAD + d];
    const float bias = __ldg(bih + r) + __ldg(bhh + r);
    const int outIdx = ((r & 15) << 2) | (r >> 4);

    constexpr int D4 = DIN / 4;
    for (int p = (tid >> 6); p < 64; p += 4) {
        const float* xp = &sx[p * XPAD];
        float acc = bias;
#pragma unroll
        for (int d4 = 0; d4 < D4; ++d4) {
            float4 v = ((const float4*)xp)[d4];
            acc = fmaf(v.x, w[d4 * 4 + 0], acc);
            acc = fmaf(v.y, w[d4 * 4 + 1], acc);
            acc = fmaf(v.z, w[d4 * 4 + 2], acc);
            acc = fmaf(v.w, w[d4 * 4 + 3], acc);
        }
#pragma unroll
        for (int d = 4 * D4; d < DIN; ++d)
            acc = fmaf(xp[d], w[d], acc);
        xg[((posBase + p) << 6) + outIdx] = acc;
    }
}

// ---------------- chunked recurrent scan (R6 core + state carry) ------------
// 16 lanes per batch, 2 batches/warp, 8 warps/CTA; grid = 16 CTAs; CSTEP steps.
__global__ void __launch_bounds__(256)
scan_chunk(const float4* __restrict__ xg,
           const float*  __restrict__ Whh,
           float*        __restrict__ hout,
           const int*    __restrict__ lengths,
           int apply_mask, int chunk,
           float* __restrict__ cst, float* __restrict__ hst)
{
    __shared__ __align__(16) float sh[8 * 2 * 32];   // [warp][parity][half*16+j]

    const int tid  = threadIdx.x;
    const int wid  = tid >> 5;
    const int lane = tid & 31;
    const int j    = lane & 15;
    const int half = lane >> 4;
    const int b    = blockIdx.x * 16 + (wid << 1) + half;

    u64 wi2[8], wf2[8], wg2[8], wo2[8];
    {
        const float2* ri = (const float2*)(Whh + ( 0 + j) * 16);
        const float2* rf = (const float2*)(Whh + (16 + j) * 16);
        const float2* rg = (const float2*)(Whh + (32 + j) * 16);
        const float2* ro = (const float2*)(Whh + (48 + j) * 16);
#pragma unroll
        for (int m = 0; m < 8; ++m) {
            float2 a = __ldg(ri + m), bb = __ldg(rf + m);
            float2 cc = __ldg(rg + m), dd = __ldg(ro + m);
            wi2[m] = pk2(a.x, a.y);
            wf2[m] = pk2(bb.x, bb.y);
            wg2[m] = pk2(cc.x, cc.y);
            wo2[m] = pk2(dd.x, dd.y);
        }
    }
    const int len = apply_mask ? lengths[b] : TT;
    const int t0  = chunk * CSTEP;

    const float4* xp = xg   + (size_t)b * TT * 16 + j;
    float*        hp = hout + (size_t)b * TT * 16 + j;

    float c, hprev;
    if (chunk == 0) { c = 0.0f; hprev = 0.0f; }
    else            { c = cst[b * 16 + j]; hprev = hst[b * 16 + j]; }

    float* shW = sh + wid * 64;
    // step s reads parity (s&1)^1, writes (s&1); s=0 reads parity 1
    shW[32 + lane] = hprev;
    __syncwarp();

    float hn = hprev;
    float4 buf[8];
#pragma unroll
    for (int u = 0; u < 8; ++u) buf[u] = __ldg(xp + (t0 + u) * 16);

    for (int sb = 0; sb < CSTEP; sb += 8) {
#pragma unroll
        for (int u = 0; u < 8; ++u) {
            const int t = t0 + sb + u;
            const float4 cur = buf[u];
            buf[u] = __ldg(xp + (t + 8) * 16);   // padded; tail never consumed

            const ulonglong2* q = (const ulonglong2*)(shW + ((u & 1) ^ 1) * 32 + half * 16);
            ulonglong2 q0 = q[0], q1 = q[1];

            u64 ai0 = pk2(cur.x, 0.0f), af0 = pk2(cur.y, 0.0f);
            u64 ag0 = pk2(cur.z, 0.0f), ao0 = pk2(cur.w, 0.0f);
            ai0 = fma2(q0.x, wi2[0], ai0);  af0 = fma2(q0.x, wf2[0], af0);
            ag0 = fma2(q0.x, wg2[0], ag0);  ao0 = fma2(q0.x, wo2[0], ao0);
            ai0 = fma2(q0.y, wi2[1], ai0);  af0 = fma2(q0.y, wf2[1], af0);
            ag0 = fma2(q0.y, wg2[1], ag0);  ao0 = fma2(q0.y, wo2[1], ao0);
            ai0 = fma2(q1.x, wi2[2], ai0);  af0 = fma2(q1.x, wf2[2], af0);
            ag0 = fma2(q1.x, wg2[2], ag0);  ao0 = fma2(q1.x, wo2[2], ao0);
            ai0 = fma2(q1.y, wi2[3], ai0);  af0 = fma2(q1.y, wf2[3], af0);
            ag0 = fma2(q1.y, wg2[3], ag0);  ao0 = fma2(q1.y, wo2[3], ao0);

            ulonglong2 q2 = q[2], q3 = q[3];
            u64 ai1 = fma2(q2.x, wi2[4], 0ull), af1 = fma2(q2.x, wf2[4], 0ull);
            u64 ag1 = fma2(q2.x, wg2[4], 0ull), ao1 = fma2(q2.x, wo2[4], 0ull);
            ai1 = fma2(q2.y, wi2[5], ai1);  af1 = fma2(q2.y, wf2[5], af1);
            ag1 = fma2(q2.y, wg2[5], ag1);  ao1 = fma2(q2.y, wo2[5], ao1);
            ai1 = fma2(q3.x, wi2[6], ai1);  af1 = fma2(q3.x, wf2[6], af1);
            ag1 = fma2(q3.x, wg2[6], ag1);  ao1 = fma2(q3.x, wo2[6], ao1);
            ai1 = fma2(q3.y, wi2[7], ai1);  af1 = fma2(q3.y, wf2[7], af1);
            ag1 = fma2(q3.y, wg2[7], ag1);  ao1 = fma2(q3.y, wo2[7], ao1);

            float l0, h0, l1, h1, l2, h2, l3, h3;
            upk2(l0, h0, add2(ai0, ai1)); float a_i = l0 + h0;
            upk2(l1, h1, add2(af0, af1)); float a_f = l1 + h1;
            upk2(l2, h2, add2(ag0, ag1)); float a_g = l2 + h2;
            upk2(l3, h3, add2(ao0, ao1)); float a_o = l3 + h3;

            float gi = f_sigm(a_i);
            float gf = f_sigm(a_f);
            float gg = f_tanh(a_g);
            float go = f_sigm(a_o);
            c = fmaf(gf, c, gi * gg);
            hn = go * f_tanh(c);

            shW[(u & 1) * 32 + half * 16 + j] = hn;
            hp[t * 16] = (t < len) ? hn : 0.0f;
            __syncwarp();
        }
    }
    cst[b * 16 + j] = c;
    hst[b * 16 + j] = hn;
}

// ---------------- BN stats --------------------------------------------------
__global__ void zero_stats_kernel() {
    if (threadIdx.x < 32) g_stats[threadIdx.x] = 0.0f;
}

__global__ void stats_kernel()
{
    __shared__ float ss[16], sq[16];
    int tid = threadIdx.x;
    if (tid < 16) { ss[tid] = 0.0f; sq[tid] = 0.0f; }
    __syncthreads();
    int j = tid & 15;
    int rpb = blockDim.x >> 4;
    float s = 0.0f, s2 = 0.0f;
    for (int pos = blockIdx.x * rpb + (tid >> 4); pos < NPOS; pos += gridDim.x * rpb) {
        float v = g_h2[(size_t)pos * 16 + j];
        s += v; s2 += v * v;
    }
    atomicAdd(&ss[j], s);
    atomicAdd(&sq[j], s2);
    __syncthreads();
    if (tid < 16) {
        atomicAdd(&g_stats[tid],      ss[tid]);
        atomicAdd(&g_stats[16 + tid], sq[tid]);
    }
}

// ---------------- fold BN into FC ------------------------------------------
__global__ void coef_kernel(const float* __restrict__ gamma,
                            const float* __restrict__ beta,
                            const float* __restrict__ fcw,
                            const float* __restrict__ fcb)
{
    __shared__ float scl[16], sht[16];
    int tid = threadIdx.x;
    if (tid < 16) {
        const float inv_n = 1.0f / (float)NPOS;
        float mean = g_stats[tid] * inv_n;
        float var  = g_stats[16 + tid] * inv_n - mean * mean;
        float s = rsqrtf(var + 1e-5f) * gamma[tid];
        scl[tid] = s;
        sht[tid] = beta[tid] - mean * s;
    }
    __syncthreads();
    if (tid < 64) {
        int o = tid >> 4, jj = tid & 15;
        g_coef[tid] = fcw[o * 16 + jj] * scl[jj];
    }
    if (tid < 4) {
        float bb = fcb[tid];
        for (int jj = 0; jj < 16; ++jj)
            bb += fcw[tid * 16 + jj] * sht[jj];
        g_coef[64 + tid] = bb;
    }
}

// ---------------- final GEMV ------------------------------------------------
__global__ void out_kernel(float* __restrict__ out)
{
    int pos = blockIdx.x * blockDim.x + threadIdx.x;
    if (pos >= NPOS) return;
    const float4* hp = (const float4*)(g_h2 + (size_t)pos * 16);
    float4 v0 = hp[0], v1 = hp[1], v2 = hp[2], v3 = hp[3];
    float hv[16] = { v0.x, v0.y, v0.z, v0.w, v1.x, v1.y, v1.z, v1.w,
                     v2.x, v2.y, v2.z, v2.w, v3.x, v3.y, v3.z, v3.w };
    float o0 = g_coef[64], o1 = g_coef[65], o2 = g_coef[66], o3 = g_coef[67];
#pragma unroll
    for (int jj = 0; jj < 16; ++jj) {
        float hvv = hv[jj];
        o0 = fmaf(hvv, g_coef[ 0 + jj], o0);
        o1 = fmaf(hvv, g_coef[16 + jj], o1);
        o2 = fmaf(hvv, g_coef[32 + jj], o2);
        o3 = fmaf(hvv, g_coef[48 + jj], o3);
    }
    float4 r = { o0, o1, o2, o3 };
    ((float4*)out)[pos] = r;
}

// ---------------- streams/events (static init: pre-main, pre-checkpoint) ----
struct PipeRes {
    cudaStream_t s[6];                 // P0,S0,P1,S1,P2,S2
    cudaEvent_t root, fin[6];
    cudaEvent_t eP0[NCHUNK], eS0[NCHUNK], eP1[NCHUNK],
                eS1[NCHUNK], eP2[NCHUNK], eS2[NCHUNK];
    PipeRes() {
        for (int i = 0; i < 6; ++i)
            cudaStreamCreateWithFlags(&s[i], cudaStreamNonBlocking);
        cudaEventCreateWithFlags(&root, cudaEventDisableTiming);
        for (int i = 0; i < 6; ++i)
            cudaEventCreateWithFlags(&fin[i], cudaEventDisableTiming);
        for (int c = 0; c < NCHUNK; ++c) {
            cudaEventCreateWithFlags(&eP0[c], cudaEventDisableTiming);
            cudaEventCreateWithFlags(&eS0[c], cudaEventDisableTiming);
            cudaEventCreateWithFlags(&eP1[c], cudaEventDisableTiming);
            cudaEventCreateWithFlags(&eS1[c], cudaEventDisableTiming);
            cudaEventCreateWithFlags(&eP2[c], cudaEventDisableTiming);
            cudaEventCreateWithFlags(&eS2[c], cudaEventDisableTiming);
        }
    }
};
static PipeRes g_res;

// ---------------- host ------------------------------------------------------
extern "C" void kernel_launch(void* const* d_in, const int* in_sizes, int n_in,
                              void* d_out, int out_size)
{
    const float* x    = (const float*)d_in[0];
    const int*   len  = (const int*)  d_in[1];
    const float* Wih0 = (const float*)d_in[2];
    const float* Whh0 = (const float*)d_in[3];
    const float* bih0 = (const float*)d_in[4];
    const float* bhh0 = (const float*)d_in[5];
    const float* Wih1 = (const float*)d_in[6];
    const float* Whh1 = (const float*)d_in[7];
    const float* bih1 = (const float*)d_in[8];
    const float* bhh1 = (const float*)d_in[9];
    const float* Wih2 = (const float*)d_in[10];
    const float* Whh2 = (const float*)d_in[11];
    const float* bih2 = (const float*)d_in[12];
    const float* bhh2 = (const float*)d_in[13];
    const float* gam  = (const float*)d_in[14];
    const float* bet  = (const float*)d_in[15];
    const float* fcw  = (const float*)d_in[16];
    const float* fcb  = (const float*)d_in[17];

    float *xg0, *xg1, *xg2, *h0, *h1, *h2, *cst, *hst;
    cudaGetSymbolAddress((void**)&xg0, g_xg0);
    cudaGetSymbolAddress((void**)&xg1, g_xg1);
    cudaGetSymbolAddress((void**)&xg2, g_xg2);
    cudaGetSymbolAddress((void**)&h0,  g_h0);
    cudaGetSymbolAddress((void**)&h1,  g_h1);
    cudaGetSymbolAddress((void**)&h2,  g_h2);
    cudaGetSymbolAddress((void**)&cst, g_cst);
    cudaGetSymbolAddress((void**)&hst, g_hst);

    cudaStream_t P0 = g_res.s[0], S0 = g_res.s[1], P1 = g_res.s[2],
                 S1 = g_res.s[3], P2 = g_res.s[4], S2 = g_res.s[5];

    // fork all worker streams from the (captured) legacy stream
    cudaEventRecord(g_res.root, 0);
    for (int i = 0; i < 6; ++i)
        cudaStreamWaitEvent(g_res.s[i], g_res.root, 0);

    // layer-0 projection chunks
    for (int c = 0; c < NCHUNK; ++c) {
        proj_chunk<DD0><<<BB * 2, 256, 0, P0>>>(x, Wih0, bih0, bhh0, xg0, c);
        cudaEventRecord(g_res.eP0[c], P0);
    }
    // layer-0 scan chunks
    for (int c = 0; c < NCHUNK; ++c) {
        cudaStreamWaitEvent(S0, g_res.eP0[c], 0);
        scan_chunk<<<16, 256, 0, S0>>>((const float4*)xg0, Whh0, h0, len, 0, c,
                                       cst + 0 * BB * HH, hst + 0 * BB * HH);
        cudaEventRecord(g_res.eS0[c], S0);
    }
    // layer-1 projection chunks (from h0)
    for (int c = 0; c < NCHUNK; ++c) {
        cudaStreamWaitEvent(P1, g_res.eS0[c], 0);
        proj_chunk<HH><<<BB * 2, 256, 0, P1>>>(h0, Wih1, bih1, bhh1, xg1, c);
        cudaEventRecord(g_res.eP1[c], P1);
    }
    // layer-1 scan chunks
    for (int c = 0; c < NCHUNK; ++c) {
        cudaStreamWaitEvent(S1, g_res.eP1[c], 0);
        scan_chunk<<<16, 256, 0, S1>>>((const float4*)xg1, Whh1, h1, len, 0, c,
                                       cst + 1 * BB * HH, hst + 1 * BB * HH);
        cudaEventRecord(g_res.eS1[c], S1);
    }
    // layer-2 projection chunks (from h1)
    for (int c = 0; c < NCHUNK; ++c) {
        cudaStreamWaitEvent(P2, g_res.eS1[c], 0);
        proj_chunk<HH><<<BB * 2, 256, 0, P2>>>(h1, Wih2, bih2, bhh2, xg2, c);
        cudaEventRecord(g_res.eP2[c], P2);
    }
    // layer-2 scan chunks (mask applied at store)
    for (int c = 0; c < NCHUNK; ++c) {
        cudaStreamWaitEvent(S2, g_res.eP2[c], 0);
        scan_chunk<<<16, 256, 0, S2>>>((const float4*)xg2, Whh2, h2, len, 1, c,
                                       cst + 2 * BB * HH, hst + 2 * BB * HH);
        cudaEventRecord(g_res.eS2[c], S2);
    }

    // join all workers back to the legacy stream
    for (int i = 0; i < 6; ++i) {
        cudaEventRecord(g_res.fin[i], g_res.s[i]);
        cudaStreamWaitEvent(0, g_res.fin[i], 0);
    }

    // epilogue on the legacy stream
    zero_stats_kernel<<<1, 32>>>();
    stats_kernel<<<1024, 256>>>();
    coef_kernel<<<1, 64>>>(gam, bet, fcw, fcb);
    out_kernel<<<NPOS / 256, 256>>>((float*)d_out);
}